// round 15
// baseline (speedup 1.0000x reference)
#include <cuda_runtime.h>
#include <cuda_fp16.h>
#include <cstdint>

#define NS 4096
#define NQ 8192
#define NR 12288
#define IND 784
#define EMB 512
#define NC 64
#define KE 832           // 784 padded to 64-multiple (1-term fp16 encoder)
#define LOG2E 1.4426950408889634f

// ------------------------- device scratch -----------------------------------
__device__ __align__(128) __half g_X[(size_t)NR * KE];      // xh
__device__ __align__(128) __half g_W[(size_t)EMB * KE];     // wh (W^T rows)
__device__ __align__(128) __half g_Q[(size_t)NQ * 512];     // qh (1024 B/row)
__device__ __align__(128) __half g_S[(size_t)NS * 512];     // sh, class-sorted rows
__device__ float g_n2p[4 * NR];
__device__ int   g_cls[NS];      // original idx -> class
__device__ int   g_rank[NS];     // original idx -> sorted pos
__device__ int   g_inv[NS];      // sorted pos -> original idx
__device__ int   g_clsS[NS];     // class at sorted pos
__device__ float g_pnum[2 * (size_t)NQ * NC];
__device__ float g_pden[2 * NQ];

// ------------------------- helpers ------------------------------------------
__device__ __forceinline__ uint32_t smem_u32(const void* p) {
    uint32_t a;
    asm("{ .reg .u64 t; cvta.to.shared.u64 t, %1; cvt.u32.u64 %0, t; }" : "=r"(a) : "l"(p));
    return a;
}
#define CP_COMMIT() asm volatile("cp.async.commit_group;" ::: "memory")
#define CP_WAIT1()  asm volatile("cp.async.wait_group 1;" ::: "memory")

__device__ __forceinline__ void ldm4(uint32_t r[4], uint32_t addr) {
    asm volatile("ldmatrix.sync.aligned.m8n8.x4.shared.b16 {%0,%1,%2,%3}, [%4];"
                 : "=r"(r[0]), "=r"(r[1]), "=r"(r[2]), "=r"(r[3]) : "r"(addr));
}
__device__ __forceinline__ void mma16816(float c[4], uint32_t a0, uint32_t a1, uint32_t a2,
                                         uint32_t a3, uint32_t b0, uint32_t b1) {
    asm volatile(
        "mma.sync.aligned.m16n8k16.row.col.f32.f16.f16.f32 "
        "{%0,%1,%2,%3}, {%4,%5,%6,%7}, {%8,%9}, {%0,%1,%2,%3};"
        : "+f"(c[0]), "+f"(c[1]), "+f"(c[2]), "+f"(c[3])
        : "r"(a0), "r"(a1), "r"(a2), "r"(a3), "r"(b0), "r"(b1));
}
// fp16-accumulator variant: D/C = 2 x f16x2 regs
__device__ __forceinline__ void mma16816h(uint32_t c[2], uint32_t a0, uint32_t a1, uint32_t a2,
                                          uint32_t a3, uint32_t b0, uint32_t b1) {
    asm volatile(
        "mma.sync.aligned.m16n8k16.row.col.f16.f16.f16.f16 "
        "{%0,%1}, {%2,%3,%4,%5}, {%6,%7}, {%0,%1};"
        : "+r"(c[0]), "+r"(c[1])
        : "r"(a0), "r"(a1), "r"(a2), "r"(a3), "r"(b0), "r"(b1));
}

// ROWS x 64 halfs (128B) global -> smem (stride 144B); THREADS-thread CTA
template <int ROWS, int THREADS>
__device__ __forceinline__ void loadT(uint32_t sdst, const char* gbase, uint32_t goff,
                                      uint32_t rs, int tid) {
#pragma unroll
    for (int i = 0; i < ROWS * 8 / THREADS; i++) {
        int u = tid + i * THREADS, r = u >> 3, j = u & 7;
        asm volatile("cp.async.cg.shared.global [%0], [%1], 16;"
                     :: "r"(sdst + r * 144 + j * 16),
                        "l"(gbase + goff + (uint32_t)r * rs + j * 16) : "memory");
    }
}

// BK=64 chunk, warp tile 32x64 (dist): fp16-acc HMMA within the chunk,
// promoted into fp32 accumulators once per chunk. 16 warps (4x4).
__device__ __forceinline__ void compute_d(uint32_t smA, uint32_t smB, int wm, int wn, int lane,
                                          float c[2][8][4]) {
    uint32_t aRow = smA + (uint32_t)((wm * 32 + (lane & 15)) * 144 + (lane >> 4) * 16);
    uint32_t bRow = smB + (uint32_t)((wn * 64 + (lane >> 4) * 8 + (lane & 7)) * 144
                                     + ((lane >> 3) & 1) * 16);
    uint32_t c16[2][8][2];
#pragma unroll
    for (int mi = 0; mi < 2; mi++)
#pragma unroll
        for (int ni = 0; ni < 8; ni++) { c16[mi][ni][0] = 0u; c16[mi][ni][1] = 0u; }
#pragma unroll
    for (int ks = 0; ks < 4; ks++) {
        uint32_t ko = (uint32_t)ks * 32;
        uint32_t a[2][4], b[4][4];
#pragma unroll
        for (int mi = 0; mi < 2; mi++) ldm4(a[mi], aRow + mi * 2304 + ko);
#pragma unroll
        for (int q = 0; q < 4; q++) ldm4(b[q], bRow + q * 2304 + ko);
#pragma unroll
        for (int mi = 0; mi < 2; mi++)
#pragma unroll
            for (int ni = 0; ni < 8; ni++)
                mma16816h(c16[mi][ni], a[mi][0], a[mi][1], a[mi][2], a[mi][3],
                          b[ni >> 1][(ni & 1) * 2], b[ni >> 1][(ni & 1) * 2 + 1]);
    }
    // promote chunk partials to fp32
#pragma unroll
    for (int mi = 0; mi < 2; mi++)
#pragma unroll
        for (int ni = 0; ni < 8; ni++) {
            float2 f0 = __half22float2(*reinterpret_cast<__half2*>(&c16[mi][ni][0]));
            float2 f1 = __half22float2(*reinterpret_cast<__half2*>(&c16[mi][ni][1]));
            c[mi][ni][0] += f0.x; c[mi][ni][1] += f0.y;
            c[mi][ni][2] += f1.x; c[mi][ni][3] += f1.y;
        }
}

// BK=64 chunk, warp tile 64x32 (enc): fp32-acc (unchanged). 8 warps (2x4).
__device__ __forceinline__ void compute_e(uint32_t smA, uint32_t smB, int wm, int wn, int lane,
                                          float c[4][4][4]) {
    uint32_t aRow = smA + (uint32_t)((wm * 64 + (lane & 15)) * 144 + (lane >> 4) * 16);
    uint32_t bRow = smB + (uint32_t)((wn * 32 + (lane >> 4) * 8 + (lane & 7)) * 144
                                     + ((lane >> 3) & 1) * 16);
#pragma unroll
    for (int ks = 0; ks < 4; ks++) {
        uint32_t ko = (uint32_t)ks * 32;
        uint32_t a[4][4], b[2][4];
#pragma unroll
        for (int mi = 0; mi < 4; mi++) ldm4(a[mi], aRow + mi * 2304 + ko);
#pragma unroll
        for (int q = 0; q < 2; q++) ldm4(b[q], bRow + q * 2304 + ko);
#pragma unroll
        for (int mi = 0; mi < 4; mi++)
#pragma unroll
            for (int ni = 0; ni < 4; ni++)
                mma16816(c[mi][ni], a[mi][0], a[mi][1], a[mi][2], a[mi][3],
                         b[ni >> 1][(ni & 1) * 2], b[ni >> 1][(ni & 1) * 2 + 1]);
    }
}

// ------------------------- smem layouts -------------------------------------
// enc: stage = A(128x144) + B(128x144) = 36864; 3 stages; 2 CTAs/SM
#define ESTG 36864
#define E_BIAS 110592
#define E_N2   111104
#define SMEM_ENC 111616
// dist: stage = A(128x144=18432) + B(256x144=36864) = 55296; 3 stages
#define DSTG 55296
#define D_SACC 165888              // 128*65 f32 = 33280
#define D_S2   199168              // 2*256 f32
#define D_CLS  201216              // 2*256 int
#define D_Q2   203264              // 128 f32
#define D_LS   203776              // 128 f32
#define SMEM_DIST 204288

// =============================================================================
// Prep: fp16 rounding of X (NR rows), W^T (EMB rows), AND class extraction
// =============================================================================
__global__ void prep_kernel(const float* __restrict__ sup, const float* __restrict__ qry,
                            const float* __restrict__ W,
                            const float* __restrict__ labels) {
    int bid = blockIdx.x;
    if (bid < NR) {
        const float* src = bid < NS ? sup + (size_t)bid * IND : qry + (size_t)(bid - NS) * IND;
        __half* dst = g_X + (size_t)bid * KE;
        for (int c = threadIdx.x; c < IND; c += 128)
            dst[c] = __float2half_rn(src[c]);
        if (threadIdx.x < KE - IND) dst[IND + threadIdx.x] = __ushort_as_half(0);
    } else if (bid < NR + EMB) {
        int n = bid - NR;
        __half* dst = g_W + (size_t)n * KE;
        for (int k = threadIdx.x; k < IND; k += 128)
            dst[k] = __float2half_rn(W[(size_t)k * EMB + n]);
        if (threadIdx.x < KE - IND) dst[IND + threadIdx.x] = __ushort_as_half(0);
    } else {
        int row = (bid - NR - EMB) * 128 + threadIdx.x;   // 32 blocks x 128 = 4096
        const float* lr = labels + (size_t)row * NC;
        int c = 0;
#pragma unroll
        for (int j = 0; j < NC; j++)
            if (lr[j] > 0.5f) c = j;
        g_cls[row] = c;
    }
}

// =============================================================================
// Deterministic stable counting sort from g_cls (16 KB, L2-resident).
// =============================================================================
__global__ __launch_bounds__(256) void rank_kernel() {
    __shared__ int cl[NS];
    __shared__ int eqs[256], lts[256];
    const int b = blockIdx.x, tid = threadIdx.x;
    for (int idx = tid; idx < NS; idx += 256) cl[idx] = g_cls[idx];
    __syncthreads();
    int e0 = 0, l0 = 0;
    const int j0 = tid * 16;
#pragma unroll
    for (int e = 0; e < 16; e++) {
        int c = cl[j0 + e];
        e0 += (c == b);
        l0 += (c < b);
    }
    eqs[tid] = e0; lts[tid] = l0;
    __syncthreads();
    for (int off = 1; off < 256; off <<= 1) {
        int ve = (tid >= off) ? eqs[tid - off] : 0;
        int vl = (tid >= off) ? lts[tid - off] : 0;
        __syncthreads();
        eqs[tid] += ve; lts[tid] += vl;
        __syncthreads();
    }
    int r = lts[255] + eqs[tid] - e0;
    for (int e = 0; e < 16; e++) {
        int j = j0 + e;
        if (cl[j] == b) {
            g_rank[j] = r;
            g_inv[r] = j;
            g_clsS[r] = b;
            r++;
        }
    }
}

// =============================================================================
// Encoder: D[128x128] = X * W^T, K=832 (pure fp16).
// 8 warps (2x4), warp tile 64x32, single-barrier 3-stage pipeline, 2 CTAs/SM.
// =============================================================================
__global__ __launch_bounds__(256, 2) void enc_kernel(const float* __restrict__ bias) {
    extern __shared__ char sm[];
    uint32_t smb = smem_u32(sm);
    const int tid = threadIdx.x, lane = tid & 31, w = tid >> 5, wm = w >> 2, wn = w & 3;
    const int m0 = blockIdx.x * 128, n0 = blockIdx.y * 128;
    float* biasS = (float*)(sm + E_BIAS);
    float* n2s = (float*)(sm + E_N2);
    if (tid < 128) { biasS[tid] = bias[n0 + tid]; n2s[tid] = 0.f; }

    const char* A = (const char*)g_X + (size_t)m0 * (KE * 2);
    const char* B = (const char*)g_W + (size_t)n0 * (KE * 2);
    const int G = KE / 64;  // 13
    loadT<128, 256>(smb, A, 0, KE * 2, tid);
    loadT<128, 256>(smb + 18432, B, 0, KE * 2, tid); CP_COMMIT();
    loadT<128, 256>(smb + ESTG, A, 128, KE * 2, tid);
    loadT<128, 256>(smb + ESTG + 18432, B, 128, KE * 2, tid); CP_COMMIT();

    float c[4][4][4];
#pragma unroll
    for (int i = 0; i < 4; i++)
#pragma unroll
        for (int j = 0; j < 4; j++)
#pragma unroll
            for (int k = 0; k < 4; k++) c[i][j][k] = 0.f;

    for (int g = 0; g < G; g++) {
        CP_WAIT1(); __syncthreads();
        int s = (g % 3) * ESTG;
        compute_e(smb + s, smb + s + 18432, wm, wn, lane, c);
        if (g + 2 < G) {
            int s2 = ((g + 2) % 3) * ESTG;
            loadT<128, 256>(smb + s2, A, (uint32_t)(g + 2) * 128, KE * 2, tid);
            loadT<128, 256>(smb + s2 + 18432, B, (uint32_t)(g + 2) * 128, KE * 2, tid);
        }
        CP_COMMIT();
    }

    float vsq[8];
#pragma unroll
    for (int i = 0; i < 8; i++) vsq[i] = 0.f;
#pragma unroll
    for (int mi = 0; mi < 4; mi++) {
        int r0 = wm * 64 + mi * 16 + (lane >> 2);
#pragma unroll
        for (int ni = 0; ni < 4; ni++) {
            int cn = wn * 32 + ni * 8 + (lane & 3) * 2;
            float b0 = biasS[cn], b1 = biasS[cn + 1];
            float v0 = c[mi][ni][0] + b0, v1 = c[mi][ni][1] + b1;
            float v2 = c[mi][ni][2] + b0, v3 = c[mi][ni][3] + b1;
            vsq[2 * mi] += v0 * v0 + v1 * v1;
            vsq[2 * mi + 1] += v2 * v2 + v3 * v3;
#pragma unroll
            for (int h = 0; h < 2; h++) {
                float x0 = h ? v2 : v0, x1 = h ? v3 : v1;
                int rg = m0 + r0 + h * 8, col = n0 + cn;
                __half h0 = __float2half_rn(x0), h1 = __float2half_rn(x1);
                uint32_t hp = ((uint32_t)__half_as_ushort(h1) << 16) | __half_as_ushort(h0);
                if (rg < NS) {
                    int sr = g_rank[rg];
                    ((uint32_t*)(g_S + (size_t)sr * 512))[col >> 1] = hp;
                } else {
                    ((uint32_t*)(g_Q + (size_t)(rg - NS) * 512))[col >> 1] = hp;
                }
            }
        }
    }
#pragma unroll
    for (int i = 0; i < 8; i++) {
        float v = vsq[i];
        v += __shfl_xor_sync(~0u, v, 1);
        v += __shfl_xor_sync(~0u, v, 2);
        if ((lane & 3) == 0)
            atomicAdd(&n2s[wm * 64 + (i >> 1) * 16 + (lane >> 2) + (i & 1) * 8], v);
    }
    __syncthreads();
    if (tid < 128) g_n2p[blockIdx.y * NR + m0 + tid] = n2s[tid];
}

__device__ __forceinline__ float pfun(float q2, float s2, float qs) {
    float d2 = fmaxf(q2 + s2 - 2.f * qs, 0.f);
    float d, p;
    asm("sqrt.approx.f32 %0, %1;" : "=f"(d) : "f"(d2));
    asm("ex2.approx.f32 %0, %1;" : "=f"(p) : "f"((32.f - d) * LOG2E));
    return p;
}

// =============================================================================
// Fused distance/softmax/aggregate. CTA: 128 queries x 2048 supports (sorted).
// 8 tiles of 256 supports x 8 K-chunks = 64 iterations. 16 warps, tile 32x64.
// fp16-acc HMMA per chunk, fp32 promotion. 3-stage pipeline, grid 128.
// =============================================================================
__global__ __launch_bounds__(512, 1) void dist_kernel() {
    extern __shared__ char sm[];
    uint32_t smb = smem_u32(sm);
    const int tid = threadIdx.x, lane = tid & 31, w = tid >> 5, wm = w >> 2, wn = w & 3;
    const int m0 = blockIdx.x * 128, half = blockIdx.y, s0 = half * 2048;
    float* sacc  = (float*)(sm + D_SACC);
    float* s2s   = (float*)(sm + D_S2);
    int*   clss  = (int*)(sm + D_CLS);
    float* q2s   = (float*)(sm + D_Q2);
    float* lsums = (float*)(sm + D_LS);

    for (int i = tid; i < 128 * 65; i += 512) sacc[i] = 0.f;
    if (tid < 128) {
        int qr = NS + m0 + tid;
        q2s[tid] = g_n2p[qr] + g_n2p[NR + qr] + g_n2p[2 * NR + qr] + g_n2p[3 * NR + qr];
        lsums[tid] = 0.f;
    }
    if (tid < 256) {
        int sc = s0 + tid, o = g_inv[sc];
        s2s[tid] = g_n2p[o] + g_n2p[NR + o] + g_n2p[2 * NR + o] + g_n2p[3 * NR + o];
        clss[tid] = g_clsS[sc];
    }
    const char* A  = (const char*)g_Q + (size_t)m0 * 1024;
    const char* Sb = (const char*)g_S + (size_t)s0 * 1024;

#define LOADG(gg) do { \
        int _s = ((gg) % 3) * DSTG; \
        uint32_t _t = (uint32_t)(gg) >> 3, _kc = (uint32_t)(gg) & 7; \
        loadT<128, 512>(smb + _s, A, _kc * 128, 1024, tid); \
        loadT<256, 512>(smb + _s + 18432, Sb, _t * 262144 + _kc * 128, 1024, tid); \
    } while (0)

    LOADG(0); CP_COMMIT();
    LOADG(1); CP_COMMIT();

    float c[2][8][4];
#pragma unroll
    for (int i = 0; i < 2; i++)
#pragma unroll
        for (int j = 0; j < 8; j++)
#pragma unroll
            for (int k = 0; k < 4; k++) c[i][j][k] = 0.f;
    float lrow[4];
#pragma unroll
    for (int i = 0; i < 4; i++) lrow[i] = 0.f;
    __syncthreads();
    float q2r[4];
#pragma unroll
    for (int i = 0; i < 4; i++)
        q2r[i] = q2s[wm * 32 + (i >> 1) * 16 + (lane >> 2) + (i & 1) * 8];

    const int jb = wn * 64 + (lane & 3) * 2;

    for (int g = 0; g < 64; g++) {
        CP_WAIT1(); __syncthreads();
        int s = (g % 3) * DSTG;
        compute_d(smb + s, smb + s + 18432, wm, wn, lane, c);
        if (g + 2 < 64) LOADG(g + 2);
        CP_COMMIT();
        if ((g & 7) == 7) {
            int t = g >> 3, slot = t & 1;
            const float* s2 = s2s + slot * 256;
            const int* cl = clss + slot * 256;
            const bool fast = (cl[jb] == cl[jb + 57]);
            const int c0 = cl[jb];
#pragma unroll
            for (int mi = 0; mi < 2; mi++) {
#pragma unroll
                for (int h = 0; h < 2; h++) {
                    int r = wm * 32 + mi * 16 + (lane >> 2) + h * 8;
                    if (fast) {
                        float lr = 0.f;
#pragma unroll
                        for (int ni = 0; ni < 8; ni++) {
#pragma unroll
                            for (int e = 0; e < 2; e++) {
                                int j = jb + ni * 8 + e;
                                lr += pfun(q2r[2 * mi + h], s2[j], c[mi][ni][2 * h + e]);
                            }
                        }
                        lrow[2 * mi + h] += lr;
                        atomicAdd(&sacc[r * 65 + c0], lr);
                    } else {
                        float lr = 0.f, acc = 0.f;
                        int cc = -1;
#pragma unroll
                        for (int ni = 0; ni < 8; ni++) {
#pragma unroll
                            for (int e = 0; e < 2; e++) {
                                int j = jb + ni * 8 + e;
                                float pv = pfun(q2r[2 * mi + h], s2[j], c[mi][ni][2 * h + e]);
                                lr += pv;
                                int cj = cl[j];
                                if (cj == cc) {
                                    acc += pv;
                                } else {
                                    if (cc >= 0) atomicAdd(&sacc[r * 65 + cc], acc);
                                    cc = cj; acc = pv;
                                }
                            }
                        }
                        atomicAdd(&sacc[r * 65 + cc], acc);
                        lrow[2 * mi + h] += lr;
                    }
                }
#pragma unroll
                for (int ni = 0; ni < 8; ni++)
#pragma unroll
                    for (int k = 0; k < 4; k++) c[mi][ni][k] = 0.f;
            }
            if (t + 1 < 8 && tid < 256) {
                int sc = s0 + (t + 1) * 256 + tid, o = g_inv[sc];
                s2s[((t + 1) & 1) * 256 + tid] =
                    g_n2p[o] + g_n2p[NR + o] + g_n2p[2 * NR + o] + g_n2p[3 * NR + o];
                clss[((t + 1) & 1) * 256 + tid] = g_clsS[sc];
            }
        }
    }
#pragma unroll
    for (int i = 0; i < 4; i++) {
        float v = lrow[i];
        v += __shfl_xor_sync(~0u, v, 1);
        v += __shfl_xor_sync(~0u, v, 2);
        if ((lane & 3) == 0)
            atomicAdd(&lsums[wm * 32 + (i >> 1) * 16 + (lane >> 2) + (i & 1) * 8], v);
    }
    __syncthreads();
    for (int i = tid; i < 128 * 64; i += 512) {
        int r = i >> 6, cc = i & 63;
        g_pnum[(size_t)half * NQ * NC + (size_t)(m0 + r) * NC + cc] = sacc[r * 65 + cc];
    }
    if (tid < 128) g_pden[half * NQ + m0 + tid] = lsums[tid];
#undef LOADG
}

// =============================================================================
// Finalize
// =============================================================================
__global__ void fin_kernel(float* __restrict__ out) {
    int i = blockIdx.x * blockDim.x + threadIdx.x;
    if (i >= NQ * NC) return;
    int q = i >> 6;
    out[i] = (g_pnum[i] + g_pnum[(size_t)NQ * NC + i]) / (g_pden[q] + g_pden[NQ + q]);
}

// =============================================================================
// Launch: prep(0), rank(1), enc(2), dist(3), fin(4)
// =============================================================================
extern "C" void kernel_launch(void* const* d_in, const int* in_sizes, int n_in,
                              void* d_out, int out_size) {
    const float* support = (const float*)d_in[0];
    const float* query   = (const float*)d_in[1];
    const float* labels  = (const float*)d_in[2];
    const float* W       = (const float*)d_in[3];
    const float* b       = (const float*)d_in[4];
    float* out = (float*)d_out;

    cudaFuncSetAttribute(enc_kernel,  cudaFuncAttributeMaxDynamicSharedMemorySize, SMEM_ENC);
    cudaFuncSetAttribute(dist_kernel, cudaFuncAttributeMaxDynamicSharedMemorySize, SMEM_DIST);

    prep_kernel<<<NR + EMB + 32, 128>>>(support, query, W, labels);
    rank_kernel<<<NC, 256>>>();
    enc_kernel<<<dim3(NR / 128, EMB / 128), 256, SMEM_ENC>>>(b);
    dist_kernel<<<dim3(NQ / 128, 2), 512, SMEM_DIST>>>();
    fin_kernel<<<(NQ * NC + 255) / 256, 256>>>(out);
}

// round 16
// speedup vs baseline: 1.1012x; 1.1012x over previous
#include <cuda_runtime.h>
#include <cuda_fp16.h>
#include <cstdint>

#define NS 4096
#define NQ 8192
#define NR 12288
#define IND 784
#define EMB 512
#define NC 64
#define KE 832           // 784 padded to 64-multiple (1-term fp16 encoder)
#define LOG2E 1.4426950408889634f

// ------------------------- device scratch -----------------------------------
__device__ __align__(128) __half g_X[(size_t)NR * KE];      // xh
__device__ __align__(128) __half g_W[(size_t)EMB * KE];     // wh (W^T rows)
__device__ __align__(128) __half g_Q[(size_t)NQ * 512];     // qh (1024 B/row)
__device__ __align__(128) __half g_S[(size_t)NS * 512];     // sh, class-sorted rows
__device__ float g_n2p[4 * NR];
__device__ int   g_cls[NS];      // original idx -> class
__device__ int   g_rank[NS];     // original idx -> sorted pos
__device__ int   g_inv[NS];      // sorted pos -> original idx
__device__ int   g_clsS[NS];     // class at sorted pos
__device__ float g_pnum[2 * (size_t)NQ * NC];
__device__ float g_pden[2 * NQ];

// ------------------------- helpers ------------------------------------------
__device__ __forceinline__ uint32_t smem_u32(const void* p) {
    uint32_t a;
    asm("{ .reg .u64 t; cvta.to.shared.u64 t, %1; cvt.u32.u64 %0, t; }" : "=r"(a) : "l"(p));
    return a;
}
#define CP_COMMIT() asm volatile("cp.async.commit_group;" ::: "memory")
#define CP_WAIT1()  asm volatile("cp.async.wait_group 1;" ::: "memory")

__device__ __forceinline__ void ldm4(uint32_t r[4], uint32_t addr) {
    asm volatile("ldmatrix.sync.aligned.m8n8.x4.shared.b16 {%0,%1,%2,%3}, [%4];"
                 : "=r"(r[0]), "=r"(r[1]), "=r"(r[2]), "=r"(r[3]) : "r"(addr));
}
__device__ __forceinline__ void mma16816(float c[4], uint32_t a0, uint32_t a1, uint32_t a2,
                                         uint32_t a3, uint32_t b0, uint32_t b1) {
    asm volatile(
        "mma.sync.aligned.m16n8k16.row.col.f32.f16.f16.f32 "
        "{%0,%1,%2,%3}, {%4,%5,%6,%7}, {%8,%9}, {%0,%1,%2,%3};"
        : "+f"(c[0]), "+f"(c[1]), "+f"(c[2]), "+f"(c[3])
        : "r"(a0), "r"(a1), "r"(a2), "r"(a3), "r"(b0), "r"(b1));
}

// ROWS x 64 halfs (128B) global -> smem (stride 144B); THREADS-thread CTA
template <int ROWS, int THREADS>
__device__ __forceinline__ void loadT(uint32_t sdst, const char* gbase, uint32_t goff,
                                      uint32_t rs, int tid) {
#pragma unroll
    for (int i = 0; i < ROWS * 8 / THREADS; i++) {
        int u = tid + i * THREADS, r = u >> 3, j = u & 7;
        asm volatile("cp.async.cg.shared.global [%0], [%1], 16;"
                     :: "r"(sdst + r * 144 + j * 16),
                        "l"(gbase + goff + (uint32_t)r * rs + j * 16) : "memory");
    }
}

// BK=64 chunk, warp tile 32x64 (dist): A tile 128 rows, B tile 256 rows. 16 warps (4x4).
__device__ __forceinline__ void compute_d(uint32_t smA, uint32_t smB, int wm, int wn, int lane,
                                          float c[2][8][4]) {
    uint32_t aRow = smA + (uint32_t)((wm * 32 + (lane & 15)) * 144 + (lane >> 4) * 16);
    uint32_t bRow = smB + (uint32_t)((wn * 64 + (lane >> 4) * 8 + (lane & 7)) * 144
                                     + ((lane >> 3) & 1) * 16);
#pragma unroll
    for (int ks = 0; ks < 4; ks++) {
        uint32_t ko = (uint32_t)ks * 32;
        uint32_t a[2][4], b[4][4];
#pragma unroll
        for (int mi = 0; mi < 2; mi++) ldm4(a[mi], aRow + mi * 2304 + ko);
#pragma unroll
        for (int q = 0; q < 4; q++) ldm4(b[q], bRow + q * 2304 + ko);
#pragma unroll
        for (int mi = 0; mi < 2; mi++)
#pragma unroll
            for (int ni = 0; ni < 8; ni++)
                mma16816(c[mi][ni], a[mi][0], a[mi][1], a[mi][2], a[mi][3],
                         b[ni >> 1][(ni & 1) * 2], b[ni >> 1][(ni & 1) * 2 + 1]);
    }
}

// BK=64 chunk, warp tile 64x32 (enc): A tile 128 rows, B tile 128 rows. 8 warps (2x4).
__device__ __forceinline__ void compute_e(uint32_t smA, uint32_t smB, int wm, int wn, int lane,
                                          float c[4][4][4]) {
    uint32_t aRow = smA + (uint32_t)((wm * 64 + (lane & 15)) * 144 + (lane >> 4) * 16);
    uint32_t bRow = smB + (uint32_t)((wn * 32 + (lane >> 4) * 8 + (lane & 7)) * 144
                                     + ((lane >> 3) & 1) * 16);
#pragma unroll
    for (int ks = 0; ks < 4; ks++) {
        uint32_t ko = (uint32_t)ks * 32;
        uint32_t a[4][4], b[2][4];
#pragma unroll
        for (int mi = 0; mi < 4; mi++) ldm4(a[mi], aRow + mi * 2304 + ko);
#pragma unroll
        for (int q = 0; q < 2; q++) ldm4(b[q], bRow + q * 2304 + ko);
#pragma unroll
        for (int mi = 0; mi < 4; mi++)
#pragma unroll
            for (int ni = 0; ni < 4; ni++)
                mma16816(c[mi][ni], a[mi][0], a[mi][1], a[mi][2], a[mi][3],
                         b[ni >> 1][(ni & 1) * 2], b[ni >> 1][(ni & 1) * 2 + 1]);
    }
}

// ------------------------- smem layouts -------------------------------------
// enc: stage = A(128x144) + B(128x144) = 36864; 3 stages; 2 CTAs/SM
#define ESTG 36864
#define E_BIAS 110592
#define E_N2   111104
#define SMEM_ENC 111616
// dist: stage = A(128x144=18432) + B(256x144=36864) = 55296; 3 stages
#define DSTG 55296
#define D_SACC 165888              // 128*65 f32 = 33280
#define D_S2   199168              // 2*256 f32
#define D_CLS  201216              // 2*256 int
#define D_Q2   203264              // 128 f32
#define D_LS   203776              // 128 f32
#define SMEM_DIST 204288

// =============================================================================
// Prep: fp16 rounding of X (NR rows), W^T (EMB rows), AND class extraction
// =============================================================================
__global__ void prep_kernel(const float* __restrict__ sup, const float* __restrict__ qry,
                            const float* __restrict__ W,
                            const float* __restrict__ labels) {
    int bid = blockIdx.x;
    if (bid < NR) {
        const float* src = bid < NS ? sup + (size_t)bid * IND : qry + (size_t)(bid - NS) * IND;
        __half* dst = g_X + (size_t)bid * KE;
        for (int c = threadIdx.x; c < IND; c += 128)
            dst[c] = __float2half_rn(src[c]);
        if (threadIdx.x < KE - IND) dst[IND + threadIdx.x] = __ushort_as_half(0);
    } else if (bid < NR + EMB) {
        int n = bid - NR;
        __half* dst = g_W + (size_t)n * KE;
        for (int k = threadIdx.x; k < IND; k += 128)
            dst[k] = __float2half_rn(W[(size_t)k * EMB + n]);
        if (threadIdx.x < KE - IND) dst[IND + threadIdx.x] = __ushort_as_half(0);
    } else {
        int row = (bid - NR - EMB) * 128 + threadIdx.x;   // 32 blocks x 128 = 4096
        const float* lr = labels + (size_t)row * NC;
        int c = 0;
#pragma unroll
        for (int j = 0; j < NC; j++)
            if (lr[j] > 0.5f) c = j;
        g_cls[row] = c;
    }
}

// =============================================================================
// Deterministic stable counting sort from g_cls (16 KB, L2-resident).
// =============================================================================
__global__ __launch_bounds__(256) void rank_kernel() {
    __shared__ int cl[NS];
    __shared__ int eqs[256], lts[256];
    const int b = blockIdx.x, tid = threadIdx.x;
    for (int idx = tid; idx < NS; idx += 256) cl[idx] = g_cls[idx];
    __syncthreads();
    int e0 = 0, l0 = 0;
    const int j0 = tid * 16;
#pragma unroll
    for (int e = 0; e < 16; e++) {
        int c = cl[j0 + e];
        e0 += (c == b);
        l0 += (c < b);
    }
    eqs[tid] = e0; lts[tid] = l0;
    __syncthreads();
    for (int off = 1; off < 256; off <<= 1) {
        int ve = (tid >= off) ? eqs[tid - off] : 0;
        int vl = (tid >= off) ? lts[tid - off] : 0;
        __syncthreads();
        eqs[tid] += ve; lts[tid] += vl;
        __syncthreads();
    }
    int r = lts[255] + eqs[tid] - e0;
    for (int e = 0; e < 16; e++) {
        int j = j0 + e;
        if (cl[j] == b) {
            g_rank[j] = r;
            g_inv[r] = j;
            g_clsS[r] = b;
            r++;
        }
    }
}

// =============================================================================
// Encoder: D[128x128] = X * W^T, K=832 (pure fp16).
// 8 warps (2x4), warp tile 64x32, single-barrier 3-stage pipeline, 2 CTAs/SM.
// =============================================================================
__global__ __launch_bounds__(256, 2) void enc_kernel(const float* __restrict__ bias) {
    extern __shared__ char sm[];
    uint32_t smb = smem_u32(sm);
    const int tid = threadIdx.x, lane = tid & 31, w = tid >> 5, wm = w >> 2, wn = w & 3;
    const int m0 = blockIdx.x * 128, n0 = blockIdx.y * 128;
    float* biasS = (float*)(sm + E_BIAS);
    float* n2s = (float*)(sm + E_N2);
    if (tid < 128) { biasS[tid] = bias[n0 + tid]; n2s[tid] = 0.f; }

    const char* A = (const char*)g_X + (size_t)m0 * (KE * 2);
    const char* B = (const char*)g_W + (size_t)n0 * (KE * 2);
    const int G = KE / 64;  // 13
    loadT<128, 256>(smb, A, 0, KE * 2, tid);
    loadT<128, 256>(smb + 18432, B, 0, KE * 2, tid); CP_COMMIT();
    loadT<128, 256>(smb + ESTG, A, 128, KE * 2, tid);
    loadT<128, 256>(smb + ESTG + 18432, B, 128, KE * 2, tid); CP_COMMIT();

    float c[4][4][4];
#pragma unroll
    for (int i = 0; i < 4; i++)
#pragma unroll
        for (int j = 0; j < 4; j++)
#pragma unroll
            for (int k = 0; k < 4; k++) c[i][j][k] = 0.f;

    for (int g = 0; g < G; g++) {
        CP_WAIT1(); __syncthreads();
        int s = (g % 3) * ESTG;
        if (g + 2 < G) {
            int s2 = ((g + 2) % 3) * ESTG;
            loadT<128, 256>(smb + s2, A, (uint32_t)(g + 2) * 128, KE * 2, tid);
            loadT<128, 256>(smb + s2 + 18432, B, (uint32_t)(g + 2) * 128, KE * 2, tid);
        }
        CP_COMMIT();
        compute_e(smb + s, smb + s + 18432, wm, wn, lane, c);
    }

    float vsq[8];
#pragma unroll
    for (int i = 0; i < 8; i++) vsq[i] = 0.f;
#pragma unroll
    for (int mi = 0; mi < 4; mi++) {
        int r0 = wm * 64 + mi * 16 + (lane >> 2);
#pragma unroll
        for (int ni = 0; ni < 4; ni++) {
            int cn = wn * 32 + ni * 8 + (lane & 3) * 2;
            float b0 = biasS[cn], b1 = biasS[cn + 1];
            float v0 = c[mi][ni][0] + b0, v1 = c[mi][ni][1] + b1;
            float v2 = c[mi][ni][2] + b0, v3 = c[mi][ni][3] + b1;
            vsq[2 * mi] += v0 * v0 + v1 * v1;
            vsq[2 * mi + 1] += v2 * v2 + v3 * v3;
#pragma unroll
            for (int h = 0; h < 2; h++) {
                float x0 = h ? v2 : v0, x1 = h ? v3 : v1;
                int rg = m0 + r0 + h * 8, col = n0 + cn;
                __half h0 = __float2half_rn(x0), h1 = __float2half_rn(x1);
                uint32_t hp = ((uint32_t)__half_as_ushort(h1) << 16) | __half_as_ushort(h0);
                if (rg < NS) {
                    int sr = g_rank[rg];
                    ((uint32_t*)(g_S + (size_t)sr * 512))[col >> 1] = hp;
                } else {
                    ((uint32_t*)(g_Q + (size_t)(rg - NS) * 512))[col >> 1] = hp;
                }
            }
        }
    }
#pragma unroll
    for (int i = 0; i < 8; i++) {
        float v = vsq[i];
        v += __shfl_xor_sync(~0u, v, 1);
        v += __shfl_xor_sync(~0u, v, 2);
        if ((lane & 3) == 0)
            atomicAdd(&n2s[wm * 64 + (i >> 1) * 16 + (lane >> 2) + (i & 1) * 8], v);
    }
    __syncthreads();
    if (tid < 128) g_n2p[blockIdx.y * NR + m0 + tid] = n2s[tid];
}

__device__ __forceinline__ float pfun(float q2, float s2, float qs) {
    float d2 = fmaxf(q2 + s2 - 2.f * qs, 0.f);
    float d, p;
    asm("sqrt.approx.f32 %0, %1;" : "=f"(d) : "f"(d2));
    asm("ex2.approx.f32 %0, %1;" : "=f"(p) : "f"((32.f - d) * LOG2E));
    return p;
}

// =============================================================================
// Fused distance/softmax/aggregate. CTA: 128 queries x 2048 supports (sorted).
// 8 tiles of 256 supports x 8 K-chunks = 64 iterations. 16 warps, tile 32x64.
// fp32-acc HMMA, 3-stage pipeline, grid 128. Loads issued before compute.
// =============================================================================
__global__ __launch_bounds__(512, 1) void dist_kernel() {
    extern __shared__ char sm[];
    uint32_t smb = smem_u32(sm);
    const int tid = threadIdx.x, lane = tid & 31, w = tid >> 5, wm = w >> 2, wn = w & 3;
    const int m0 = blockIdx.x * 128, half = blockIdx.y, s0 = half * 2048;
    float* sacc  = (float*)(sm + D_SACC);
    float* s2s   = (float*)(sm + D_S2);
    int*   clss  = (int*)(sm + D_CLS);
    float* q2s   = (float*)(sm + D_Q2);
    float* lsums = (float*)(sm + D_LS);

    for (int i = tid; i < 128 * 65; i += 512) sacc[i] = 0.f;
    if (tid < 128) {
        int qr = NS + m0 + tid;
        q2s[tid] = g_n2p[qr] + g_n2p[NR + qr] + g_n2p[2 * NR + qr] + g_n2p[3 * NR + qr];
        lsums[tid] = 0.f;
    }
    if (tid < 256) {
        int sc = s0 + tid, o = g_inv[sc];
        s2s[tid] = g_n2p[o] + g_n2p[NR + o] + g_n2p[2 * NR + o] + g_n2p[3 * NR + o];
        clss[tid] = g_clsS[sc];
    }
    const char* A  = (const char*)g_Q + (size_t)m0 * 1024;
    const char* Sb = (const char*)g_S + (size_t)s0 * 1024;

#define LOADG(gg) do { \
        int _s = ((gg) % 3) * DSTG; \
        uint32_t _t = (uint32_t)(gg) >> 3, _kc = (uint32_t)(gg) & 7; \
        loadT<128, 512>(smb + _s, A, _kc * 128, 1024, tid); \
        loadT<256, 512>(smb + _s + 18432, Sb, _t * 262144 + _kc * 128, 1024, tid); \
    } while (0)

    LOADG(0); CP_COMMIT();
    LOADG(1); CP_COMMIT();

    float c[2][8][4];
#pragma unroll
    for (int i = 0; i < 2; i++)
#pragma unroll
        for (int j = 0; j < 8; j++)
#pragma unroll
            for (int k = 0; k < 4; k++) c[i][j][k] = 0.f;
    float lrow[4];
#pragma unroll
    for (int i = 0; i < 4; i++) lrow[i] = 0.f;
    __syncthreads();
    float q2r[4];
#pragma unroll
    for (int i = 0; i < 4; i++)
        q2r[i] = q2s[wm * 32 + (i >> 1) * 16 + (lane >> 2) + (i & 1) * 8];

    const int jb = wn * 64 + (lane & 3) * 2;

    for (int g = 0; g < 64; g++) {
        CP_WAIT1(); __syncthreads();
        int s = (g % 3) * DSTG;
        if (g + 2 < 64) LOADG(g + 2);
        CP_COMMIT();
        compute_d(smb + s, smb + s + 18432, wm, wn, lane, c);
        if ((g & 7) == 7) {
            int t = g >> 3, slot = t & 1;
            const float* s2 = s2s + slot * 256;
            const int* cl = clss + slot * 256;
            const bool fast = (cl[jb] == cl[jb + 57]);
            const int c0 = cl[jb];
#pragma unroll
            for (int mi = 0; mi < 2; mi++) {
#pragma unroll
                for (int h = 0; h < 2; h++) {
                    int r = wm * 32 + mi * 16 + (lane >> 2) + h * 8;
                    if (fast) {
                        float lr = 0.f;
#pragma unroll
                        for (int ni = 0; ni < 8; ni++) {
#pragma unroll
                            for (int e = 0; e < 2; e++) {
                                int j = jb + ni * 8 + e;
                                lr += pfun(q2r[2 * mi + h], s2[j], c[mi][ni][2 * h + e]);
                            }
                        }
                        lrow[2 * mi + h] += lr;
                        atomicAdd(&sacc[r * 65 + c0], lr);
                    } else {
                        float lr = 0.f, acc = 0.f;
                        int cc = -1;
#pragma unroll
                        for (int ni = 0; ni < 8; ni++) {
#pragma unroll
                            for (int e = 0; e < 2; e++) {
                                int j = jb + ni * 8 + e;
                                float pv = pfun(q2r[2 * mi + h], s2[j], c[mi][ni][2 * h + e]);
                                lr += pv;
                                int cj = cl[j];
                                if (cj == cc) {
                                    acc += pv;
                                } else {
                                    if (cc >= 0) atomicAdd(&sacc[r * 65 + cc], acc);
                                    cc = cj; acc = pv;
                                }
                            }
                        }
                        atomicAdd(&sacc[r * 65 + cc], acc);
                        lrow[2 * mi + h] += lr;
                    }
                }
#pragma unroll
                for (int ni = 0; ni < 8; ni++)
#pragma unroll
                    for (int k = 0; k < 4; k++) c[mi][ni][k] = 0.f;
            }
            if (t + 1 < 8 && tid < 256) {
                int sc = s0 + (t + 1) * 256 + tid, o = g_inv[sc];
                s2s[((t + 1) & 1) * 256 + tid] =
                    g_n2p[o] + g_n2p[NR + o] + g_n2p[2 * NR + o] + g_n2p[3 * NR + o];
                clss[((t + 1) & 1) * 256 + tid] = g_clsS[sc];
            }
        }
    }
#pragma unroll
    for (int i = 0; i < 4; i++) {
        float v = lrow[i];
        v += __shfl_xor_sync(~0u, v, 1);
        v += __shfl_xor_sync(~0u, v, 2);
        if ((lane & 3) == 0)
            atomicAdd(&lsums[wm * 32 + (i >> 1) * 16 + (lane >> 2) + (i & 1) * 8], v);
    }
    __syncthreads();
    for (int i = tid; i < 128 * 64; i += 512) {
        int r = i >> 6, cc = i & 63;
        g_pnum[(size_t)half * NQ * NC + (size_t)(m0 + r) * NC + cc] = sacc[r * 65 + cc];
    }
    if (tid < 128) g_pden[half * NQ + m0 + tid] = lsums[tid];
#undef LOADG
}

// =============================================================================
// Finalize
// =============================================================================
__global__ void fin_kernel(float* __restrict__ out) {
    int i = blockIdx.x * blockDim.x + threadIdx.x;
    if (i >= NQ * NC) return;
    int q = i >> 6;
    out[i] = (g_pnum[i] + g_pnum[(size_t)NQ * NC + i]) / (g_pden[q] + g_pden[NQ + q]);
}

// =============================================================================
// Launch: prep(0), rank(1), enc(2), dist(3), fin(4)
// =============================================================================
extern "C" void kernel_launch(void* const* d_in, const int* in_sizes, int n_in,
                              void* d_out, int out_size) {
    const float* support = (const float*)d_in[0];
    const float* query   = (const float*)d_in[1];
    const float* labels  = (const float*)d_in[2];
    const float* W       = (const float*)d_in[3];
    const float* b       = (const float*)d_in[4];
    float* out = (float*)d_out;

    cudaFuncSetAttribute(enc_kernel,  cudaFuncAttributeMaxDynamicSharedMemorySize, SMEM_ENC);
    cudaFuncSetAttribute(dist_kernel, cudaFuncAttributeMaxDynamicSharedMemorySize, SMEM_DIST);

    prep_kernel<<<NR + EMB + 32, 128>>>(support, query, W, labels);
    rank_kernel<<<NC, 256>>>();
    enc_kernel<<<dim3(NR / 128, EMB / 128), 256, SMEM_ENC>>>(b);
    dist_kernel<<<dim3(NQ / 128, 2), 512, SMEM_DIST>>>();
    fin_kernel<<<(NQ * NC + 255) / 256, 256>>>(out);
}

// round 17
// speedup vs baseline: 1.1776x; 1.0694x over previous
#include <cuda_runtime.h>
#include <cuda_fp16.h>
#include <cstdint>

#define NS 4096
#define NQ 8192
#define NR 12288
#define IND 784
#define EMB 512
#define NC 64
#define KE 832           // 784 padded to 64-multiple (1-term fp16 encoder)
#define LOG2E 1.4426950408889634f

// ------------------------- device scratch -----------------------------------
__device__ __align__(128) __half g_X[(size_t)NR * KE];      // xh
__device__ __align__(128) __half g_W[(size_t)EMB * KE];     // wh (W^T rows)
__device__ __align__(128) __half g_Q[(size_t)NQ * 512];     // qh (1024 B/row)
__device__ __align__(128) __half g_S[(size_t)NS * 512];     // sh, class-sorted rows
__device__ float g_n2p[4 * NR];
__device__ int   g_cls[NS];      // original idx -> class
__device__ int   g_rank[NS];     // original idx -> sorted pos
__device__ int   g_inv[NS];      // sorted pos -> original idx
__device__ int   g_clsS[NS];     // class at sorted pos
__device__ float g_pnum[2 * (size_t)NQ * NC];
__device__ float g_pden[2 * NQ];
__device__ unsigned g_done[NQ / 128];   // per query-tile arrival counter

// ------------------------- helpers ------------------------------------------
__device__ __forceinline__ uint32_t smem_u32(const void* p) {
    uint32_t a;
    asm("{ .reg .u64 t; cvta.to.shared.u64 t, %1; cvt.u32.u64 %0, t; }" : "=r"(a) : "l"(p));
    return a;
}
#define CP_COMMIT() asm volatile("cp.async.commit_group;" ::: "memory")
#define CP_WAIT1()  asm volatile("cp.async.wait_group 1;" ::: "memory")

__device__ __forceinline__ void ldm4(uint32_t r[4], uint32_t addr) {
    asm volatile("ldmatrix.sync.aligned.m8n8.x4.shared.b16 {%0,%1,%2,%3}, [%4];"
                 : "=r"(r[0]), "=r"(r[1]), "=r"(r[2]), "=r"(r[3]) : "r"(addr));
}
__device__ __forceinline__ void mma16816(float c[4], uint32_t a0, uint32_t a1, uint32_t a2,
                                         uint32_t a3, uint32_t b0, uint32_t b1) {
    asm volatile(
        "mma.sync.aligned.m16n8k16.row.col.f32.f16.f16.f32 "
        "{%0,%1,%2,%3}, {%4,%5,%6,%7}, {%8,%9}, {%0,%1,%2,%3};"
        : "+f"(c[0]), "+f"(c[1]), "+f"(c[2]), "+f"(c[3])
        : "r"(a0), "r"(a1), "r"(a2), "r"(a3), "r"(b0), "r"(b1));
}

// ROWS x 64 halfs (128B) global -> smem (stride 144B); THREADS-thread CTA
template <int ROWS, int THREADS>
__device__ __forceinline__ void loadT(uint32_t sdst, const char* gbase, uint32_t goff,
                                      uint32_t rs, int tid) {
#pragma unroll
    for (int i = 0; i < ROWS * 8 / THREADS; i++) {
        int u = tid + i * THREADS, r = u >> 3, j = u & 7;
        asm volatile("cp.async.cg.shared.global [%0], [%1], 16;"
                     :: "r"(sdst + r * 144 + j * 16),
                        "l"(gbase + goff + (uint32_t)r * rs + j * 16) : "memory");
    }
}

// BK=64 chunk, warp tile 32x64 (dist): A tile 128 rows, B tile 256 rows. 16 warps (4x4).
__device__ __forceinline__ void compute_d(uint32_t smA, uint32_t smB, int wm, int wn, int lane,
                                          float c[2][8][4]) {
    uint32_t aRow = smA + (uint32_t)((wm * 32 + (lane & 15)) * 144 + (lane >> 4) * 16);
    uint32_t bRow = smB + (uint32_t)((wn * 64 + (lane >> 4) * 8 + (lane & 7)) * 144
                                     + ((lane >> 3) & 1) * 16);
#pragma unroll
    for (int ks = 0; ks < 4; ks++) {
        uint32_t ko = (uint32_t)ks * 32;
        uint32_t a[2][4], b[4][4];
#pragma unroll
        for (int mi = 0; mi < 2; mi++) ldm4(a[mi], aRow + mi * 2304 + ko);
#pragma unroll
        for (int q = 0; q < 4; q++) ldm4(b[q], bRow + q * 2304 + ko);
#pragma unroll
        for (int mi = 0; mi < 2; mi++)
#pragma unroll
            for (int ni = 0; ni < 8; ni++)
                mma16816(c[mi][ni], a[mi][0], a[mi][1], a[mi][2], a[mi][3],
                         b[ni >> 1][(ni & 1) * 2], b[ni >> 1][(ni & 1) * 2 + 1]);
    }
}

// BK=64 chunk, warp tile 64x32 (enc): A tile 128 rows, B tile 128 rows. 8 warps (2x4).
__device__ __forceinline__ void compute_e(uint32_t smA, uint32_t smB, int wm, int wn, int lane,
                                          float c[4][4][4]) {
    uint32_t aRow = smA + (uint32_t)((wm * 64 + (lane & 15)) * 144 + (lane >> 4) * 16);
    uint32_t bRow = smB + (uint32_t)((wn * 32 + (lane >> 4) * 8 + (lane & 7)) * 144
                                     + ((lane >> 3) & 1) * 16);
#pragma unroll
    for (int ks = 0; ks < 4; ks++) {
        uint32_t ko = (uint32_t)ks * 32;
        uint32_t a[4][4], b[2][4];
#pragma unroll
        for (int mi = 0; mi < 4; mi++) ldm4(a[mi], aRow + mi * 2304 + ko);
#pragma unroll
        for (int q = 0; q < 2; q++) ldm4(b[q], bRow + q * 2304 + ko);
#pragma unroll
        for (int mi = 0; mi < 4; mi++)
#pragma unroll
            for (int ni = 0; ni < 4; ni++)
                mma16816(c[mi][ni], a[mi][0], a[mi][1], a[mi][2], a[mi][3],
                         b[ni >> 1][(ni & 1) * 2], b[ni >> 1][(ni & 1) * 2 + 1]);
    }
}

// ------------------------- smem layouts -------------------------------------
// enc: stage = A(128x144) + B(128x144) = 36864; 3 stages; 2 CTAs/SM
#define ESTG 36864
#define E_BIAS 110592
#define E_N2   111104
#define SMEM_ENC 111616
// dist: stage = A(128x144=18432) + B(256x144=36864) = 55296; 3 stages
#define DSTG 55296
#define D_SACC 165888              // 128*65 f32 = 33280
#define D_S2   199168              // 2*256 f32
#define D_CLS  201216              // 2*256 int
#define D_Q2   203264              // 128 f32
#define D_LS   203776              // 128 f32
#define D_FLAG 204288              // 4 B
#define SMEM_DIST 204352

// =============================================================================
// Prep: fp16 rounding of X (NR rows), W^T (EMB rows), AND class extraction
// =============================================================================
__global__ void prep_kernel(const float* __restrict__ sup, const float* __restrict__ qry,
                            const float* __restrict__ W,
                            const float* __restrict__ labels) {
    int bid = blockIdx.x;
    if (bid < NR) {
        const float* src = bid < NS ? sup + (size_t)bid * IND : qry + (size_t)(bid - NS) * IND;
        __half* dst = g_X + (size_t)bid * KE;
        for (int c = threadIdx.x; c < IND; c += 128)
            dst[c] = __float2half_rn(src[c]);
        if (threadIdx.x < KE - IND) dst[IND + threadIdx.x] = __ushort_as_half(0);
    } else if (bid < NR + EMB) {
        int n = bid - NR;
        __half* dst = g_W + (size_t)n * KE;
        for (int k = threadIdx.x; k < IND; k += 128)
            dst[k] = __float2half_rn(W[(size_t)k * EMB + n]);
        if (threadIdx.x < KE - IND) dst[IND + threadIdx.x] = __ushort_as_half(0);
    } else {
        int row = (bid - NR - EMB) * 128 + threadIdx.x;   // 32 blocks x 128 = 4096
        const float* lr = labels + (size_t)row * NC;
        int c = 0;
#pragma unroll
        for (int j = 0; j < NC; j++)
            if (lr[j] > 0.5f) c = j;
        g_cls[row] = c;
    }
}

// =============================================================================
// Deterministic stable counting sort from g_cls (16 KB, L2-resident).
// Also zeroes g_done for this launch (block b, tid 0).
// =============================================================================
__global__ __launch_bounds__(256) void rank_kernel() {
    __shared__ int cl[NS];
    __shared__ int eqs[256], lts[256];
    const int b = blockIdx.x, tid = threadIdx.x;
    if (tid == 0) g_done[b] = 0u;
    for (int idx = tid; idx < NS; idx += 256) cl[idx] = g_cls[idx];
    __syncthreads();
    int e0 = 0, l0 = 0;
    const int j0 = tid * 16;
#pragma unroll
    for (int e = 0; e < 16; e++) {
        int c = cl[j0 + e];
        e0 += (c == b);
        l0 += (c < b);
    }
    eqs[tid] = e0; lts[tid] = l0;
    __syncthreads();
    for (int off = 1; off < 256; off <<= 1) {
        int ve = (tid >= off) ? eqs[tid - off] : 0;
        int vl = (tid >= off) ? lts[tid - off] : 0;
        __syncthreads();
        eqs[tid] += ve; lts[tid] += vl;
        __syncthreads();
    }
    int r = lts[255] + eqs[tid] - e0;
    for (int e = 0; e < 16; e++) {
        int j = j0 + e;
        if (cl[j] == b) {
            g_rank[j] = r;
            g_inv[r] = j;
            g_clsS[r] = b;
            r++;
        }
    }
}

// =============================================================================
// Encoder: D[128x128] = X * W^T, K=832 (pure fp16).
// 8 warps (2x4), warp tile 64x32, single-barrier 3-stage pipeline, 2 CTAs/SM.
// =============================================================================
__global__ __launch_bounds__(256, 2) void enc_kernel(const float* __restrict__ bias) {
    extern __shared__ char sm[];
    uint32_t smb = smem_u32(sm);
    const int tid = threadIdx.x, lane = tid & 31, w = tid >> 5, wm = w >> 2, wn = w & 3;
    const int m0 = blockIdx.x * 128, n0 = blockIdx.y * 128;
    float* biasS = (float*)(sm + E_BIAS);
    float* n2s = (float*)(sm + E_N2);
    if (tid < 128) { biasS[tid] = bias[n0 + tid]; n2s[tid] = 0.f; }

    const char* A = (const char*)g_X + (size_t)m0 * (KE * 2);
    const char* B = (const char*)g_W + (size_t)n0 * (KE * 2);
    const int G = KE / 64;  // 13
    loadT<128, 256>(smb, A, 0, KE * 2, tid);
    loadT<128, 256>(smb + 18432, B, 0, KE * 2, tid); CP_COMMIT();
    loadT<128, 256>(smb + ESTG, A, 128, KE * 2, tid);
    loadT<128, 256>(smb + ESTG + 18432, B, 128, KE * 2, tid); CP_COMMIT();

    float c[4][4][4];
#pragma unroll
    for (int i = 0; i < 4; i++)
#pragma unroll
        for (int j = 0; j < 4; j++)
#pragma unroll
            for (int k = 0; k < 4; k++) c[i][j][k] = 0.f;

    for (int g = 0; g < G; g++) {
        CP_WAIT1(); __syncthreads();
        int s = (g % 3) * ESTG;
        compute_e(smb + s, smb + s + 18432, wm, wn, lane, c);
        if (g + 2 < G) {
            int s2 = ((g + 2) % 3) * ESTG;
            loadT<128, 256>(smb + s2, A, (uint32_t)(g + 2) * 128, KE * 2, tid);
            loadT<128, 256>(smb + s2 + 18432, B, (uint32_t)(g + 2) * 128, KE * 2, tid);
        }
        CP_COMMIT();
    }

    float vsq[8];
#pragma unroll
    for (int i = 0; i < 8; i++) vsq[i] = 0.f;
#pragma unroll
    for (int mi = 0; mi < 4; mi++) {
        int r0 = wm * 64 + mi * 16 + (lane >> 2);
#pragma unroll
        for (int ni = 0; ni < 4; ni++) {
            int cn = wn * 32 + ni * 8 + (lane & 3) * 2;
            float b0 = biasS[cn], b1 = biasS[cn + 1];
            float v0 = c[mi][ni][0] + b0, v1 = c[mi][ni][1] + b1;
            float v2 = c[mi][ni][2] + b0, v3 = c[mi][ni][3] + b1;
            vsq[2 * mi] += v0 * v0 + v1 * v1;
            vsq[2 * mi + 1] += v2 * v2 + v3 * v3;
#pragma unroll
            for (int h = 0; h < 2; h++) {
                float x0 = h ? v2 : v0, x1 = h ? v3 : v1;
                int rg = m0 + r0 + h * 8, col = n0 + cn;
                __half h0 = __float2half_rn(x0), h1 = __float2half_rn(x1);
                uint32_t hp = ((uint32_t)__half_as_ushort(h1) << 16) | __half_as_ushort(h0);
                if (rg < NS) {
                    int sr = g_rank[rg];
                    ((uint32_t*)(g_S + (size_t)sr * 512))[col >> 1] = hp;
                } else {
                    ((uint32_t*)(g_Q + (size_t)(rg - NS) * 512))[col >> 1] = hp;
                }
            }
        }
    }
#pragma unroll
    for (int i = 0; i < 8; i++) {
        float v = vsq[i];
        v += __shfl_xor_sync(~0u, v, 1);
        v += __shfl_xor_sync(~0u, v, 2);
        if ((lane & 3) == 0)
            atomicAdd(&n2s[wm * 64 + (i >> 1) * 16 + (lane >> 2) + (i & 1) * 8], v);
    }
    __syncthreads();
    if (tid < 128) g_n2p[blockIdx.y * NR + m0 + tid] = n2s[tid];
}

__device__ __forceinline__ float pfun(float q2, float s2, float qs) {
    float d2 = fmaxf(q2 + s2 - 2.f * qs, 0.f);
    float d, p;
    asm("sqrt.approx.f32 %0, %1;" : "=f"(d) : "f"(d2));
    asm("ex2.approx.f32 %0, %1;" : "=f"(p) : "f"((32.f - d) * LOG2E));
    return p;
}

// =============================================================================
// Fused distance/softmax/aggregate + in-kernel finalize.
// CTA: 128 queries x 2048 supports (sorted). 64 iterations, 16 warps, 32x64.
// Second-arriving CTA of each query tile combines both halves and writes out.
// =============================================================================
__global__ __launch_bounds__(512, 1) void dist_kernel(float* __restrict__ out) {
    extern __shared__ char sm[];
    uint32_t smb = smem_u32(sm);
    const int tid = threadIdx.x, lane = tid & 31, w = tid >> 5, wm = w >> 2, wn = w & 3;
    const int m0 = blockIdx.x * 128, half = blockIdx.y, s0 = half * 2048;
    float* sacc  = (float*)(sm + D_SACC);
    float* s2s   = (float*)(sm + D_S2);
    int*   clss  = (int*)(sm + D_CLS);
    float* q2s   = (float*)(sm + D_Q2);
    float* lsums = (float*)(sm + D_LS);
    unsigned* flag = (unsigned*)(sm + D_FLAG);

    for (int i = tid; i < 128 * 65; i += 512) sacc[i] = 0.f;
    if (tid < 128) {
        int qr = NS + m0 + tid;
        q2s[tid] = g_n2p[qr] + g_n2p[NR + qr] + g_n2p[2 * NR + qr] + g_n2p[3 * NR + qr];
        lsums[tid] = 0.f;
    }
    if (tid < 256) {
        int sc = s0 + tid, o = g_inv[sc];
        s2s[tid] = g_n2p[o] + g_n2p[NR + o] + g_n2p[2 * NR + o] + g_n2p[3 * NR + o];
        clss[tid] = g_clsS[sc];
    }
    const char* A  = (const char*)g_Q + (size_t)m0 * 1024;
    const char* Sb = (const char*)g_S + (size_t)s0 * 1024;

#define LOADG(gg) do { \
        int _s = ((gg) % 3) * DSTG; \
        uint32_t _t = (uint32_t)(gg) >> 3, _kc = (uint32_t)(gg) & 7; \
        loadT<128, 512>(smb + _s, A, _kc * 128, 1024, tid); \
        loadT<256, 512>(smb + _s + 18432, Sb, _t * 262144 + _kc * 128, 1024, tid); \
    } while (0)

    LOADG(0); CP_COMMIT();
    LOADG(1); CP_COMMIT();

    float c[2][8][4];
#pragma unroll
    for (int i = 0; i < 2; i++)
#pragma unroll
        for (int j = 0; j < 8; j++)
#pragma unroll
            for (int k = 0; k < 4; k++) c[i][j][k] = 0.f;
    float lrow[4];
#pragma unroll
    for (int i = 0; i < 4; i++) lrow[i] = 0.f;
    __syncthreads();
    float q2r[4];
#pragma unroll
    for (int i = 0; i < 4; i++)
        q2r[i] = q2s[wm * 32 + (i >> 1) * 16 + (lane >> 2) + (i & 1) * 8];

    const int jb = wn * 64 + (lane & 3) * 2;

    for (int g = 0; g < 64; g++) {
        CP_WAIT1(); __syncthreads();
        int s = (g % 3) * DSTG;
        compute_d(smb + s, smb + s + 18432, wm, wn, lane, c);
        if (g + 2 < 64) LOADG(g + 2);
        CP_COMMIT();
        if ((g & 7) == 7) {
            int t = g >> 3, slot = t & 1;
            const float* s2 = s2s + slot * 256;
            const int* cl = clss + slot * 256;
            const bool fast = (cl[jb] == cl[jb + 57]);
            const int c0 = cl[jb];
#pragma unroll
            for (int mi = 0; mi < 2; mi++) {
#pragma unroll
                for (int h = 0; h < 2; h++) {
                    int r = wm * 32 + mi * 16 + (lane >> 2) + h * 8;
                    if (fast) {
                        float lr = 0.f;
#pragma unroll
                        for (int ni = 0; ni < 8; ni++) {
#pragma unroll
                            for (int e = 0; e < 2; e++) {
                                int j = jb + ni * 8 + e;
                                lr += pfun(q2r[2 * mi + h], s2[j], c[mi][ni][2 * h + e]);
                            }
                        }
                        lrow[2 * mi + h] += lr;
                        atomicAdd(&sacc[r * 65 + c0], lr);
                    } else {
                        float lr = 0.f, acc = 0.f;
                        int cc = -1;
#pragma unroll
                        for (int ni = 0; ni < 8; ni++) {
#pragma unroll
                            for (int e = 0; e < 2; e++) {
                                int j = jb + ni * 8 + e;
                                float pv = pfun(q2r[2 * mi + h], s2[j], c[mi][ni][2 * h + e]);
                                lr += pv;
                                int cj = cl[j];
                                if (cj == cc) {
                                    acc += pv;
                                } else {
                                    if (cc >= 0) atomicAdd(&sacc[r * 65 + cc], acc);
                                    cc = cj; acc = pv;
                                }
                            }
                        }
                        atomicAdd(&sacc[r * 65 + cc], acc);
                        lrow[2 * mi + h] += lr;
                    }
                }
#pragma unroll
                for (int ni = 0; ni < 8; ni++)
#pragma unroll
                    for (int k = 0; k < 4; k++) c[mi][ni][k] = 0.f;
            }
            if (t + 1 < 8 && tid < 256) {
                int sc = s0 + (t + 1) * 256 + tid, o = g_inv[sc];
                s2s[((t + 1) & 1) * 256 + tid] =
                    g_n2p[o] + g_n2p[NR + o] + g_n2p[2 * NR + o] + g_n2p[3 * NR + o];
                clss[((t + 1) & 1) * 256 + tid] = g_clsS[sc];
            }
        }
    }
#pragma unroll
    for (int i = 0; i < 4; i++) {
        float v = lrow[i];
        v += __shfl_xor_sync(~0u, v, 1);
        v += __shfl_xor_sync(~0u, v, 2);
        if ((lane & 3) == 0)
            atomicAdd(&lsums[wm * 32 + (i >> 1) * 16 + (lane >> 2) + (i & 1) * 8], v);
    }
    __syncthreads();
    for (int i = tid; i < 128 * 64; i += 512) {
        int r = i >> 6, cc = i & 63;
        g_pnum[(size_t)half * NQ * NC + (size_t)(m0 + r) * NC + cc] = sacc[r * 65 + cc];
    }
    if (tid < 128) g_pden[half * NQ + m0 + tid] = lsums[tid];

    // ---- in-kernel finalize: second CTA of this query tile combines halves ---
    __threadfence();
    __syncthreads();
    if (tid == 0) *flag = atomicAdd(&g_done[blockIdx.x], 1u);
    __syncthreads();
    if (*flag == 1u) {
        __threadfence();
        for (int i = tid; i < 128 * 64; i += 512) {
            int q = m0 + (i >> 6), cc = i & 63;
            float den = __ldcg(&g_pden[q]) + __ldcg(&g_pden[NQ + q]);
            float num = __ldcg(&g_pnum[(size_t)q * NC + cc]) +
                        __ldcg(&g_pnum[(size_t)NQ * NC + (size_t)q * NC + cc]);
            out[(size_t)q * NC + cc] = num / den;
        }
    }
#undef LOADG
}

// =============================================================================
// Launch: prep(0), rank(1), enc(2), dist(3)
// =============================================================================
extern "C" void kernel_launch(void* const* d_in, const int* in_sizes, int n_in,
                              void* d_out, int out_size) {
    const float* support = (const float*)d_in[0];
    const float* query   = (const float*)d_in[1];
    const float* labels  = (const float*)d_in[2];
    const float* W       = (const float*)d_in[3];
    const float* b       = (const float*)d_in[4];
    float* out = (float*)d_out;

    cudaFuncSetAttribute(enc_kernel,  cudaFuncAttributeMaxDynamicSharedMemorySize, SMEM_ENC);
    cudaFuncSetAttribute(dist_kernel, cudaFuncAttributeMaxDynamicSharedMemorySize, SMEM_DIST);

    prep_kernel<<<NR + EMB + 32, 128>>>(support, query, W, labels);
    rank_kernel<<<NC, 256>>>();
    enc_kernel<<<dim3(NR / 128, EMB / 128), 256, SMEM_ENC>>>(b);
    dist_kernel<<<dim3(NQ / 128, 2), 512, SMEM_DIST>>>(out);
}